// round 10
// baseline (speedup 1.0000x reference)
#include <cuda_runtime.h>
#include <cuda_bf16.h>
#include <math_constants.h>
#include <cstdint>

// Problem constants (fixed by reference): B=2, S=2048, E=1024, H=16, D=64
#define BSZ   2
#define SEQ   2048
#define EMB   1024
#define NHEAD 16
#define HDIM  64
#define ROWS  (BSZ * SEQ)          // 4096
#define QKV_N (3 * EMB)            // 3072

// Scratch (allocation-free rule: __device__ globals)
static __device__ float g_qkv[ROWS * QKV_N];    // [4096, 3072] (tf32-rounded)
static __device__ float g_attn[ROWS * EMB];     // [4096, 1024] (tf32-rounded)
static __device__ float g_xc[ROWS * EMB];       // x, tf32-rounded
static __device__ float g_wqt[QKV_N * EMB];     // W_qkv^T [3072,1024], tf32-rounded
static __device__ float g_wot[EMB * EMB];       // W_out^T [1024,1024], tf32-rounded
static __device__ float g_vt[BSZ * NHEAD * HDIM * SEQ];  // per-head V^T [b][h][d][s]

// ---------------------------------------------------------------------------
// helpers
// ---------------------------------------------------------------------------
__device__ __forceinline__ uint32_t smem_to_u32(const void* p) {
    uint32_t a;
    asm("{ .reg .u64 t; cvta.to.shared.u64 t, %1; cvt.u32.u64 %0, t; }" : "=r"(a) : "l"(p));
    return a;
}
// cvt.rna.tf32.f32 writes a .b32 destination (tf32 is a bit pattern)
__device__ __forceinline__ float rna_tf32(float x) {
    uint32_t r;
    asm("cvt.rna.tf32.f32 %0, %1;" : "=r"(r) : "f"(x));
    return __uint_as_float(r);
}
__device__ __forceinline__ void cp16(uint32_t d, const void* s) {
    asm volatile("cp.async.cg.shared.global [%0], [%1], 16;" :: "r"(d), "l"(s));
}
// warp-level tf32 MMA (sm_80+; works at compute_100)
__device__ __forceinline__ void mma_tf32(float* c, const uint32_t* a, const uint32_t* b) {
    asm volatile("mma.sync.aligned.m16n8k8.row.col.f32.tf32.tf32.f32 "
                 "{%0,%1,%2,%3}, {%4,%5,%6,%7}, {%8,%9}, {%0,%1,%2,%3};"
                 : "+f"(c[0]), "+f"(c[1]), "+f"(c[2]), "+f"(c[3])
                 : "r"(a[0]), "r"(a[1]), "r"(a[2]), "r"(a[3]),
                   "r"(b[0]), "r"(b[1]));
}

// ---------------------------------------------------------------------------
// Prep kernels: tf32-rna rounding (+ transpose for weights)
// ---------------------------------------------------------------------------
__global__ void cvt_rna_kernel(const float4* __restrict__ in, float4* __restrict__ out, int n4) {
    int i = blockIdx.x * blockDim.x + threadIdx.x;
    if (i < n4) {
        float4 v = in[i];
        v.x = rna_tf32(v.x); v.y = rna_tf32(v.y);
        v.z = rna_tf32(v.z); v.w = rna_tf32(v.w);
        out[i] = v;
    }
}

// in: [R,C] row-major  ->  out: [C,R] row-major, rna-rounded
__global__ void transpose_cvt_kernel(const float* __restrict__ in, float* __restrict__ out,
                                     int R, int C) {
    __shared__ float t[32][33];
    int c0 = blockIdx.x * 32, r0 = blockIdx.y * 32;
    int tx = threadIdx.x, ty = threadIdx.y;
#pragma unroll
    for (int i = 0; i < 32; i += 8)
        t[ty + i][tx] = in[(size_t)(r0 + ty + i) * C + c0 + tx];
    __syncthreads();
#pragma unroll
    for (int i = 0; i < 32; i += 8)
        out[(size_t)(c0 + ty + i) * R + r0 + tx] = rna_tf32(t[tx][ty + i]);
}

// Per-head V transpose: g_qkv V slab [b*S+s][2048 + h*64 + d] -> g_vt[(b,h,d)][s]
// (values already tf32-rounded by the QKV GEMM epilogue)
__global__ void vt_transpose_kernel(const float* __restrict__ qkv, float* __restrict__ vt) {
    __shared__ float t[32][33];
    const int bh = blockIdx.z;            // b*16 + h
    const int b = bh >> 4, h = bh & 15;
    const int s0 = blockIdx.x * 32, d0 = blockIdx.y * 32;
    const int tx = threadIdx.x, ty = threadIdx.y;
    const float* in = qkv + (size_t)(b * SEQ) * QKV_N + 2 * EMB + h * HDIM;
#pragma unroll
    for (int i = 0; i < 32; i += 8)
        t[ty + i][tx] = in[(size_t)(s0 + ty + i) * QKV_N + d0 + tx];
    __syncthreads();
    float* outp = vt + ((size_t)bh * HDIM + d0) * SEQ + s0;
#pragma unroll
    for (int i = 0; i < 32; i += 8)
        outp[(size_t)(ty + i) * SEQ + tx] = t[tx][ty + i];
}

// ---------------------------------------------------------------------------
// tf32 warp-MMA GEMM + bias: C[M,N] = A[M,K] @ Bt[N,K]^T + bias[N]
// CTA tile 128x128, 8 warps (2x4), each warp 64x32 (4x4 m16n8k8 tiles).
// Scalar fragment loads (round-6 proven: 203us, tensor 46.9%).
// ROUND: rna-round the output (for tensors feeding later tf32 MMAs).
// ---------------------------------------------------------------------------
#define RS        36                       // smem row stride in floats
#define ASTG      (128 * RS)               // words per operand stage (4608)
#define STG_WORDS (2 * ASTG)               // A + B per stage (9216)
#define GK_DSMEM  (2 * STG_WORDS * 4)      // 73728 B

template <bool ROUND>
__global__ void __launch_bounds__(256, 2)
gemm_tc_kernel(const float* __restrict__ A, const float* __restrict__ Bt,
               const float* __restrict__ bias, float* __restrict__ C,
               int K, int N)
{
    extern __shared__ float sh[];
    const int tid = threadIdx.x;
    const int wid = tid >> 5, lane = tid & 31;
    const int g = lane >> 2, t = lane & 3;
    const int row0 = blockIdx.y * 128;
    const int col0 = blockIdx.x * 128;
    const int mbase = (wid & 1) * 64;
    const int nbase = (wid >> 1) * 32;
    const int NK = K / 32;
    const uint32_t sb = smem_to_u32(sh);

    auto load_stage = [&](int j, int p) {
        const float* Ab = A + (size_t)row0 * K + j * 32;
        const float* Bb = Bt + (size_t)col0 * K + j * 32;
        uint32_t abase = sb + p * (STG_WORDS * 4);
        uint32_t bbase = abase + ASTG * 4;
#pragma unroll
        for (int i = 0; i < 4; i++) {
            int c = tid + 256 * i;
            int row = c >> 3, c8 = c & 7;
            cp16(abase + row * (RS * 4) + c8 * 16, Ab + (size_t)row * K + c8 * 4);
            cp16(bbase + row * (RS * 4) + c8 * 16, Bb + (size_t)row * K + c8 * 4);
        }
        asm volatile("cp.async.commit_group;");
    };

    float acc[4][4][4];
#pragma unroll
    for (int mt = 0; mt < 4; mt++)
#pragma unroll
        for (int nt = 0; nt < 4; nt++)
#pragma unroll
            for (int i = 0; i < 4; i++) acc[mt][nt][i] = 0.0f;

    load_stage(0, 0);
    load_stage(1, 1);

    for (int j = 0; j < NK; j++) {
        const int p = j & 1;
        asm volatile("cp.async.wait_group 1;");
        __syncthreads();

        const float* As = sh + p * STG_WORDS;
        const float* Bs = As + ASTG;
#pragma unroll
        for (int ks = 0; ks < 4; ks++) {
            const int kc = ks * 8;
            uint32_t a[4][4], b[4][2];
#pragma unroll
            for (int mt = 0; mt < 4; mt++) {
                int r0 = (mbase + mt * 16 + g) * RS + kc + t;
                a[mt][0] = __float_as_uint(As[r0]);
                a[mt][1] = __float_as_uint(As[r0 + 8 * RS]);
                a[mt][2] = __float_as_uint(As[r0 + 4]);
                a[mt][3] = __float_as_uint(As[r0 + 8 * RS + 4]);
            }
#pragma unroll
            for (int nt = 0; nt < 4; nt++) {
                int r0 = (nbase + nt * 8 + g) * RS + kc + t;
                b[nt][0] = __float_as_uint(Bs[r0]);
                b[nt][1] = __float_as_uint(Bs[r0 + 4]);
            }
#pragma unroll
            for (int mt = 0; mt < 4; mt++)
#pragma unroll
                for (int nt = 0; nt < 4; nt++)
                    mma_tf32(acc[mt][nt], a[mt], b[nt]);
        }
        __syncthreads();
        if (j + 2 < NK) load_stage(j + 2, p);
        else asm volatile("cp.async.commit_group;");   // keep group count in step
    }

    // epilogue: c0/c1 -> (row, col..col+1), c2/c3 -> (row+8, ...)
#pragma unroll
    for (int mt = 0; mt < 4; mt++) {
        const int row = row0 + mbase + mt * 16 + g;
#pragma unroll
        for (int nt = 0; nt < 4; nt++) {
            const int col = col0 + nbase + nt * 8 + t * 2;
            const float b0 = bias[col], b1 = bias[col + 1];
            float2 v0, v1;
            if (ROUND) {
                v0 = { rna_tf32(acc[mt][nt][0] + b0), rna_tf32(acc[mt][nt][1] + b1) };
                v1 = { rna_tf32(acc[mt][nt][2] + b0), rna_tf32(acc[mt][nt][3] + b1) };
            } else {
                v0 = { acc[mt][nt][0] + b0, acc[mt][nt][1] + b1 };
                v1 = { acc[mt][nt][2] + b0, acc[mt][nt][3] + b1 };
            }
            *(float2*)&C[(size_t)row * N + col] = v0;
            *(float2*)&C[(size_t)(row + 8) * N + col] = v1;
        }
    }
}

// ---------------------------------------------------------------------------
// Tensor-core flash attention (non-causal, sm_scale = 1/8).
// CTA: 128 q-rows x one head; 8 warps, each owns 16 q-rows; 2 CTAs/SM.
// K-tile 64 keys, cp.async double-buffered.
// QK^T: K-frags LDS.128-vectorized via k-remap kappa(s,t,h)=32(s/4)+8t+2(s%4)+h.
// P.V:  register-direct P (no smem round-trip) + PRE-TRANSPOSED V (g_vt):
//       B-frag reads Vs[(ot*8+g)*VT_STR + 8s+2t] as contiguous float2 (LDS.64).
//       VT_STR=72: banks (8g+8s+2t) mod 32 — 16 distinct even banks per phase,
//       conflict-free. V LSU ops per lane per tile: 128 LDS.32 -> 64 LDS.64.
// ---------------------------------------------------------------------------
#define KTL    64
#define KS_STR 68     // K frag LDS.128: quarter-warp phases hit disjoint bank groups
#define VT_STR 72     // V^T LDS.64 bank pattern conflict-free (72 mod 32 = 8)
#define PS_STR 68     // Q staging
#define SM_K0  0
#define SM_K1  (64 * KS_STR)
#define SM_V0  (2 * 64 * KS_STR)
#define SM_V1  (SM_V0 + 64 * VT_STR)
#define SM_Q   (SM_V0 + 2 * 64 * VT_STR)
#define ATTN_SMEM_FLOATS (SM_Q + 128 * PS_STR)
#define ATTN_SMEM_BYTES  (ATTN_SMEM_FLOATS * 4)   // 106496 B -> 2 CTAs/SM

__global__ void __launch_bounds__(256, 2)
attn_tc_kernel(const float* __restrict__ qkv, const float* __restrict__ vt,
               float* __restrict__ out)
{
    extern __shared__ float sh[];
    const uint32_t sb = smem_to_u32(sh);
    const int tid = threadIdx.x, wid = tid >> 5, lane = tid & 31;
    const int g = lane >> 2, t = lane & 3;
    const int h = blockIdx.y, b = blockIdx.z;
    const int q0 = blockIdx.x * 128;
    const size_t rowbase = (size_t)(b * SEQ) * QKV_N;
    const float* qbase = qkv + rowbase + (size_t)q0 * QKV_N + h * HDIM;
    const float* vtbase = vt + ((size_t)(b * NHEAD + h) * HDIM) * SEQ;

    // stage Q[128,64], build register fragments
    {
#pragma unroll
        for (int i = 0; i < 8; i++) {
            int c = tid + 256 * i;              // 2048 float4 chunks
            int row = c >> 4, c16 = c & 15;
            cp16(sb + (SM_Q + row * PS_STR) * 4 + c16 * 16,
                 qbase + (size_t)row * QKV_N + c16 * 4);
        }
        asm volatile("cp.async.commit_group;");
        asm volatile("cp.async.wait_group 0;");
        __syncthreads();
    }
    // Q fragments, indexed by kappa(s,t,h) = 32*(s/4) + 8t + 2*(s%4) + h
    uint32_t qf[8][4];
    {
        const float* Qs = sh + SM_Q;
        const int r0 = (wid * 16 + g) * PS_STR;
#pragma unroll
        for (int s = 0; s < 8; s++) {
            int k0 = 32 * (s >> 2) + 8 * t + 2 * (s & 3);
            qf[s][0] = __float_as_uint(Qs[r0 + k0] * 0.125f);
            qf[s][1] = __float_as_uint(Qs[r0 + 8 * PS_STR + k0] * 0.125f);
            qf[s][2] = __float_as_uint(Qs[r0 + k0 + 1] * 0.125f);
            qf[s][3] = __float_as_uint(Qs[r0 + 8 * PS_STR + k0 + 1] * 0.125f);
        }
    }
    __syncthreads();

    float oacc[8][4];
#pragma unroll
    for (int nt = 0; nt < 8; nt++)
#pragma unroll
        for (int i = 0; i < 4; i++) oacc[nt][i] = 0.0f;
    float m0 = -CUDART_INF_F, m1 = -CUDART_INF_F, l0 = 0.0f, l1 = 0.0f;

    auto load_kv = [&](int kt2, int p) {
        const float* kb = qkv + rowbase + (size_t)(kt2 * KTL) * QKV_N + EMB + h * HDIM;
        const float* vb = vtbase + kt2 * KTL;       // V^T rows: dims, keys contiguous
        uint32_t kdst = sb + (p ? SM_K1 : SM_K0) * 4;
        uint32_t vdst = sb + (p ? SM_V1 : SM_V0) * 4;
#pragma unroll
        for (int i = 0; i < 4; i++) {
            int c = tid + 256 * i;              // 1024 float4 chunks each
            int row = c >> 4, c16 = c & 15;
            cp16(kdst + row * (KS_STR * 4) + c16 * 16, kb + (size_t)row * QKV_N + c16 * 4);
            cp16(vdst + row * (VT_STR * 4) + c16 * 16, vb + (size_t)row * SEQ + c16 * 4);
        }
        asm volatile("cp.async.commit_group;");
    };

    load_kv(0, 0);
    load_kv(1, 1);

    for (int kt = 0; kt < SEQ / KTL; kt++) {
        const int p = kt & 1;
        asm volatile("cp.async.wait_group 1;");
        __syncthreads();
        const float* Ks = sh + (p ? SM_K1 : SM_K0);
        const float* Vs = sh + (p ? SM_V1 : SM_V0);

        // S = Q @ K^T  — K frags vectorized (LDS.128), nt in groups of 4
        float sacc[8][4];
#pragma unroll
        for (int nt = 0; nt < 8; nt++)
#pragma unroll
            for (int i = 0; i < 4; i++) sacc[nt][i] = 0.0f;
#pragma unroll
        for (int blk = 0; blk < 2; blk++)
#pragma unroll
        for (int hf = 0; hf < 2; hf++) {
            const int kc = 32 * blk + 8 * t + 4 * hf;
#pragma unroll
            for (int ng = 0; ng < 2; ng++) {
                float4 kv[4];
#pragma unroll
                for (int n4 = 0; n4 < 4; n4++)
                    kv[n4] = *(const float4*)&Ks[((ng * 4 + n4) * 8 + g) * KS_STR + kc];
#pragma unroll
                for (int sh2 = 0; sh2 < 2; sh2++) {
                    const int s = 4 * blk + 2 * hf + sh2;
#pragma unroll
                    for (int n4 = 0; n4 < 4; n4++) {
                        const float* be = (const float*)&kv[n4];
                        uint32_t bfrag[2];
                        bfrag[0] = __float_as_uint(be[2 * sh2]);
                        bfrag[1] = __float_as_uint(be[2 * sh2 + 1]);
                        mma_tf32(sacc[ng * 4 + n4], qf[s], bfrag);
                    }
                }
            }
        }

        // online softmax (rows g and g+8 of this warp's block)
        float mt0 = -CUDART_INF_F, mt1 = -CUDART_INF_F;
#pragma unroll
        for (int nt = 0; nt < 8; nt++) {
            mt0 = fmaxf(mt0, fmaxf(sacc[nt][0], sacc[nt][1]));
            mt1 = fmaxf(mt1, fmaxf(sacc[nt][2], sacc[nt][3]));
        }
        mt0 = fmaxf(mt0, __shfl_xor_sync(0xffffffffu, mt0, 1));
        mt0 = fmaxf(mt0, __shfl_xor_sync(0xffffffffu, mt0, 2));
        mt1 = fmaxf(mt1, __shfl_xor_sync(0xffffffffu, mt1, 1));
        mt1 = fmaxf(mt1, __shfl_xor_sync(0xffffffffu, mt1, 2));

        const float mn0 = fmaxf(m0, mt0), mn1 = fmaxf(m1, mt1);
        const float al0 = __expf(m0 - mn0), al1 = __expf(m1 - mn1);
        m0 = mn0; m1 = mn1;

        float s0 = 0.0f, s1 = 0.0f;
#pragma unroll
        for (int nt = 0; nt < 8; nt++) {
            float p00 = __expf(sacc[nt][0] - mn0);
            float p01 = __expf(sacc[nt][1] - mn0);
            float p10 = __expf(sacc[nt][2] - mn1);
            float p11 = __expf(sacc[nt][3] - mn1);
            s0 += p00 + p01;
            s1 += p10 + p11;
            // keep rounded P in registers — they ARE the PV A-fragments
            sacc[nt][0] = rna_tf32(p00);
            sacc[nt][1] = rna_tf32(p01);
            sacc[nt][2] = rna_tf32(p10);
            sacc[nt][3] = rna_tf32(p11);
            oacc[nt][0] *= al0; oacc[nt][1] *= al0;
            oacc[nt][2] *= al1; oacc[nt][3] *= al1;
        }
        s0 += __shfl_xor_sync(0xffffffffu, s0, 1);
        s0 += __shfl_xor_sync(0xffffffffu, s0, 2);
        s1 += __shfl_xor_sync(0xffffffffu, s1, 1);
        s1 += __shfl_xor_sync(0xffffffffu, s1, 2);
        l0 = l0 * al0 + s0;
        l1 = l1 * al1 + s1;

        // O += P @ V — register-direct A-frags; V^T B-frags as LDS.64
#pragma unroll
        for (int s = 0; s < 8; s++) {
            uint32_t a[4];
            a[0] = __float_as_uint(sacc[s][0]);
            a[1] = __float_as_uint(sacc[s][2]);
            a[2] = __float_as_uint(sacc[s][1]);
            a[3] = __float_as_uint(sacc[s][3]);
            const int k0 = 8 * s + 2 * t;
#pragma unroll
            for (int ot = 0; ot < 8; ot++) {
                float2 v2 = *(const float2*)&Vs[(ot * 8 + g) * VT_STR + k0];
                uint32_t bb[2];
                bb[0] = __float_as_uint(v2.x);
                bb[1] = __float_as_uint(v2.y);
                mma_tf32(oacc[ot], a, bb);
            }
        }
        __syncthreads();   // everyone done with buffer p
        if (kt + 2 < SEQ / KTL) load_kv(kt + 2, p);
        else asm volatile("cp.async.commit_group;");
    }

    // epilogue: normalize, rna-round (feeds tf32 out-projection), write [B,S,E]
    const float inv0 = 1.0f / l0, inv1 = 1.0f / l1;
    float* orow0 = out + (size_t)(b * SEQ + q0 + wid * 16 + g) * EMB + h * HDIM;
    float* orow1 = orow0 + (size_t)8 * EMB;
#pragma unroll
    for (int nt = 0; nt < 8; nt++) {
        const int col = nt * 8 + 2 * t;
        float2 v0 = { rna_tf32(oacc[nt][0] * inv0), rna_tf32(oacc[nt][1] * inv0) };
        float2 v1 = { rna_tf32(oacc[nt][2] * inv1), rna_tf32(oacc[nt][3] * inv1) };
        *(float2*)&orow0[col] = v0;
        *(float2*)&orow1[col] = v1;
    }
}

// ---------------------------------------------------------------------------
// launch
// ---------------------------------------------------------------------------
extern "C" void kernel_launch(void* const* d_in, const int* in_sizes, int n_in,
                              void* d_out, int out_size)
{
    const float* x     = (const float*)d_in[0];  // [2,2048,1024]
    const float* W_qkv = (const float*)d_in[1];  // [1024,3072]
    const float* b_qkv = (const float*)d_in[2];  // [3072]
    const float* W_out = (const float*)d_in[3];  // [1024,1024]
    const float* b_out = (const float*)d_in[4];  // [1024]
    float* out = (float*)d_out;                  // [2,2048,1024]

    float *qkv, *attn, *xc, *wqt, *wot, *vt;
    cudaGetSymbolAddress((void**)&qkv,  g_qkv);
    cudaGetSymbolAddress((void**)&attn, g_attn);
    cudaGetSymbolAddress((void**)&xc,   g_xc);
    cudaGetSymbolAddress((void**)&wqt,  g_wqt);
    cudaGetSymbolAddress((void**)&wot,  g_wot);
    cudaGetSymbolAddress((void**)&vt,   g_vt);

    // 0) prep: tf32-rna rounding of x, transposed+rounded weights
    cvt_rna_kernel<<<(ROWS * EMB / 4 + 255) / 256, 256>>>((const float4*)x, (float4*)xc, ROWS * EMB / 4);
    transpose_cvt_kernel<<<dim3(QKV_N / 32, EMB / 32), dim3(32, 8)>>>(W_qkv, wqt, EMB, QKV_N);
    transpose_cvt_kernel<<<dim3(EMB / 32, EMB / 32), dim3(32, 8)>>>(W_out, wot, EMB, EMB);

    cudaFuncSetAttribute(gemm_tc_kernel<true>,
                         cudaFuncAttributeMaxDynamicSharedMemorySize, GK_DSMEM);
    cudaFuncSetAttribute(gemm_tc_kernel<false>,
                         cudaFuncAttributeMaxDynamicSharedMemorySize, GK_DSMEM);
    cudaFuncSetAttribute(attn_tc_kernel,
                         cudaFuncAttributeMaxDynamicSharedMemorySize, ATTN_SMEM_BYTES);

    // 1) QKV projection (rounded output -> q,k,v are tf32 patterns)
    gemm_tc_kernel<true><<<dim3(QKV_N / 128, ROWS / 128), 256, GK_DSMEM>>>(
        xc, wqt, b_qkv, qkv, EMB, QKV_N);

    // 1b) per-head V transpose for the PV MMA operand
    vt_transpose_kernel<<<dim3(SEQ / 32, HDIM / 32, BSZ * NHEAD), dim3(32, 8)>>>(qkv, vt);

    // 2) tensor-core flash attention
    attn_tc_kernel<<<dim3(SEQ / 128, NHEAD, BSZ), 256, ATTN_SMEM_BYTES>>>(qkv, vt, attn);

    // 3) output projection (exact fp32 output)
    gemm_tc_kernel<false><<<dim3(EMB / 128, ROWS / 128), 256, GK_DSMEM>>>(
        attn, wot, b_out, out, EMB, EMB);
}

// round 11
// speedup vs baseline: 1.0002x; 1.0002x over previous
#include <cuda_runtime.h>
#include <cuda_bf16.h>
#include <math_constants.h>
#include <cstdint>

// Problem constants (fixed by reference): B=2, S=2048, E=1024, H=16, D=64
#define BSZ   2
#define SEQ   2048
#define EMB   1024
#define NHEAD 16
#define HDIM  64
#define ROWS  (BSZ * SEQ)          // 4096
#define QKV_N (3 * EMB)            // 3072

// Scratch (allocation-free rule: __device__ globals)
static __device__ float g_qkv[ROWS * QKV_N];    // [4096, 3072] (tf32-rounded)
static __device__ float g_attn[ROWS * EMB];     // [4096, 1024] (tf32-rounded)
static __device__ float g_xc[ROWS * EMB];       // x, tf32-rounded
static __device__ float g_wqt[QKV_N * EMB];     // W_qkv^T [3072,1024], tf32-rounded
static __device__ float g_wot[EMB * EMB];       // W_out^T [1024,1024], tf32-rounded

// ---------------------------------------------------------------------------
// helpers
// ---------------------------------------------------------------------------
__device__ __forceinline__ uint32_t smem_to_u32(const void* p) {
    uint32_t a;
    asm("{ .reg .u64 t; cvta.to.shared.u64 t, %1; cvt.u32.u64 %0, t; }" : "=r"(a) : "l"(p));
    return a;
}
// cvt.rna.tf32.f32 writes a .b32 destination (tf32 is a bit pattern)
__device__ __forceinline__ float rna_tf32(float x) {
    uint32_t r;
    asm("cvt.rna.tf32.f32 %0, %1;" : "=r"(r) : "f"(x));
    return __uint_as_float(r);
}
__device__ __forceinline__ uint32_t rna_tf32_u(float x) {
    uint32_t r;
    asm("cvt.rna.tf32.f32 %0, %1;" : "=r"(r) : "f"(x));
    return r;
}
__device__ __forceinline__ void cp16(uint32_t d, const void* s) {
    asm volatile("cp.async.cg.shared.global [%0], [%1], 16;" :: "r"(d), "l"(s));
}
// warp-level tf32 MMA (sm_80+; works at compute_100)
__device__ __forceinline__ void mma_tf32(float* c, const uint32_t* a, const uint32_t* b) {
    asm volatile("mma.sync.aligned.m16n8k8.row.col.f32.tf32.tf32.f32 "
                 "{%0,%1,%2,%3}, {%4,%5,%6,%7}, {%8,%9}, {%0,%1,%2,%3};"
                 : "+f"(c[0]), "+f"(c[1]), "+f"(c[2]), "+f"(c[3])
                 : "r"(a[0]), "r"(a[1]), "r"(a[2]), "r"(a[3]),
                   "r"(b[0]), "r"(b[1]));
}

// ---------------------------------------------------------------------------
// Prep kernels: tf32-rna rounding (+ transpose for weights)
// ---------------------------------------------------------------------------
__global__ void cvt_rna_kernel(const float4* __restrict__ in, float4* __restrict__ out, int n4) {
    int i = blockIdx.x * blockDim.x + threadIdx.x;
    if (i < n4) {
        float4 v = in[i];
        v.x = rna_tf32(v.x); v.y = rna_tf32(v.y);
        v.z = rna_tf32(v.z); v.w = rna_tf32(v.w);
        out[i] = v;
    }
}

// in: [R,C] row-major  ->  out: [C,R] row-major, rna-rounded
__global__ void transpose_cvt_kernel(const float* __restrict__ in, float* __restrict__ out,
                                     int R, int C) {
    __shared__ float t[32][33];
    int c0 = blockIdx.x * 32, r0 = blockIdx.y * 32;
    int tx = threadIdx.x, ty = threadIdx.y;
#pragma unroll
    for (int i = 0; i < 32; i += 8)
        t[ty + i][tx] = in[(size_t)(r0 + ty + i) * C + c0 + tx];
    __syncthreads();
#pragma unroll
    for (int i = 0; i < 32; i += 8)
        out[(size_t)(c0 + ty + i) * R + r0 + tx] = rna_tf32(t[tx][ty + i]);
}

// ---------------------------------------------------------------------------
// tf32 warp-MMA GEMM + bias: C[M,N] = A[M,K] @ Bt[N,K]^T + bias[N]
// CTA tile 128x128, 8 warps (2x4), each warp 64x32 (4x4 m16n8k8 tiles).
// Scalar fragment loads (round-6 proven: ~197-204us, tensor 47%).
// ROUND: rna-round the output (for tensors feeding later tf32 MMAs).
// ---------------------------------------------------------------------------
#define RS        36                       // smem row stride in floats
#define ASTG      (128 * RS)               // words per operand stage (4608)
#define STG_WORDS (2 * ASTG)               // A + B per stage (9216)
#define GK_DSMEM  (2 * STG_WORDS * 4)      // 73728 B

template <bool ROUND>
__global__ void __launch_bounds__(256, 2)
gemm_tc_kernel(const float* __restrict__ A, const float* __restrict__ Bt,
               const float* __restrict__ bias, float* __restrict__ C,
               int K, int N)
{
    extern __shared__ float sh[];
    const int tid = threadIdx.x;
    const int wid = tid >> 5, lane = tid & 31;
    const int g = lane >> 2, t = lane & 3;
    const int row0 = blockIdx.y * 128;
    const int col0 = blockIdx.x * 128;
    const int mbase = (wid & 1) * 64;
    const int nbase = (wid >> 1) * 32;
    const int NK = K / 32;
    const uint32_t sb = smem_to_u32(sh);

    auto load_stage = [&](int j, int p) {
        const float* Ab = A + (size_t)row0 * K + j * 32;
        const float* Bb = Bt + (size_t)col0 * K + j * 32;
        uint32_t abase = sb + p * (STG_WORDS * 4);
        uint32_t bbase = abase + ASTG * 4;
#pragma unroll
        for (int i = 0; i < 4; i++) {
            int c = tid + 256 * i;
            int row = c >> 3, c8 = c & 7;
            cp16(abase + row * (RS * 4) + c8 * 16, Ab + (size_t)row * K + c8 * 4);
            cp16(bbase + row * (RS * 4) + c8 * 16, Bb + (size_t)row * K + c8 * 4);
        }
        asm volatile("cp.async.commit_group;");
    };

    float acc[4][4][4];
#pragma unroll
    for (int mt = 0; mt < 4; mt++)
#pragma unroll
        for (int nt = 0; nt < 4; nt++)
#pragma unroll
            for (int i = 0; i < 4; i++) acc[mt][nt][i] = 0.0f;

    load_stage(0, 0);
    load_stage(1, 1);

    for (int j = 0; j < NK; j++) {
        const int p = j & 1;
        asm volatile("cp.async.wait_group 1;");
        __syncthreads();

        const float* As = sh + p * STG_WORDS;
        const float* Bs = As + ASTG;
#pragma unroll
        for (int ks = 0; ks < 4; ks++) {
            const int kc = ks * 8;
            uint32_t a[4][4], b[4][2];
#pragma unroll
            for (int mt = 0; mt < 4; mt++) {
                int r0 = (mbase + mt * 16 + g) * RS + kc + t;
                a[mt][0] = __float_as_uint(As[r0]);
                a[mt][1] = __float_as_uint(As[r0 + 8 * RS]);
                a[mt][2] = __float_as_uint(As[r0 + 4]);
                a[mt][3] = __float_as_uint(As[r0 + 8 * RS + 4]);
            }
#pragma unroll
            for (int nt = 0; nt < 4; nt++) {
                int r0 = (nbase + nt * 8 + g) * RS + kc + t;
                b[nt][0] = __float_as_uint(Bs[r0]);
                b[nt][1] = __float_as_uint(Bs[r0 + 4]);
            }
#pragma unroll
            for (int mt = 0; mt < 4; mt++)
#pragma unroll
                for (int nt = 0; nt < 4; nt++)
                    mma_tf32(acc[mt][nt], a[mt], b[nt]);
        }
        __syncthreads();
        if (j + 2 < NK) load_stage(j + 2, p);
        else asm volatile("cp.async.commit_group;");   // keep group count in step
    }

    // epilogue: c0/c1 -> (row, col..col+1), c2/c3 -> (row+8, ...)
#pragma unroll
    for (int mt = 0; mt < 4; mt++) {
        const int row = row0 + mbase + mt * 16 + g;
#pragma unroll
        for (int nt = 0; nt < 4; nt++) {
            const int col = col0 + nbase + nt * 8 + t * 2;
            const float b0 = bias[col], b1 = bias[col + 1];
            float2 v0, v1;
            if (ROUND) {
                v0 = { rna_tf32(acc[mt][nt][0] + b0), rna_tf32(acc[mt][nt][1] + b1) };
                v1 = { rna_tf32(acc[mt][nt][2] + b0), rna_tf32(acc[mt][nt][3] + b1) };
            } else {
                v0 = { acc[mt][nt][0] + b0, acc[mt][nt][1] + b1 };
                v1 = { acc[mt][nt][2] + b0, acc[mt][nt][3] + b1 };
            }
            *(float2*)&C[(size_t)row * N + col] = v0;
            *(float2*)&C[(size_t)(row + 8) * N + col] = v1;
        }
    }
}

// ---------------------------------------------------------------------------
// Tensor-core flash attention (non-causal, sm_scale = 1/8).
// CTA: 128 q-rows x one head; 8 warps, each owns 16 q-rows; 2 CTAs/SM.
// K-tile 64 keys, cp.async double-buffered (round-9 V path: row-major, VS_STR=68).
// QK^T: K-frags LDS.128-vectorized via k-remap kappa(s,t,h)=32(s/4)+8t+2(s%4)+h.
// P.V:  register-direct P, and SOFTMAX FUSED WITH PV: per step nt, compute its
//       4 exps + rna then immediately issue the 8 PV mmas — the first tensor op
//       lands after ~4 exps instead of after the whole softmax block, and the
//       remaining exps/sums/shfls execute in the shadow of PV tensor work.
// ---------------------------------------------------------------------------
#define KTL    64
#define KS_STR 68     // K frag LDS.128: quarter-warp phases hit disjoint bank groups
#define VS_STR 68     // V LDS.32 bank pattern (8t+g) mod 32: conflict-free
#define PS_STR 68     // Q staging
#define SM_K0  0
#define SM_K1  (64 * KS_STR)
#define SM_V0  (2 * 64 * KS_STR)
#define SM_V1  (SM_V0 + 64 * VS_STR)
#define SM_Q   (SM_V0 + 2 * 64 * VS_STR)
#define ATTN_SMEM_FLOATS (SM_Q + 128 * PS_STR)
#define ATTN_SMEM_BYTES  (ATTN_SMEM_FLOATS * 4)

__global__ void __launch_bounds__(256, 2)
attn_tc_kernel(const float* __restrict__ qkv, float* __restrict__ out)
{
    extern __shared__ float sh[];
    const uint32_t sb = smem_to_u32(sh);
    const int tid = threadIdx.x, wid = tid >> 5, lane = tid & 31;
    const int g = lane >> 2, t = lane & 3;
    const int h = blockIdx.y, b = blockIdx.z;
    const int q0 = blockIdx.x * 128;
    const size_t rowbase = (size_t)(b * SEQ) * QKV_N;
    const float* qbase = qkv + rowbase + (size_t)q0 * QKV_N + h * HDIM;

    // stage Q[128,64], build register fragments
    {
#pragma unroll
        for (int i = 0; i < 8; i++) {
            int c = tid + 256 * i;              // 2048 float4 chunks
            int row = c >> 4, c16 = c & 15;
            cp16(sb + (SM_Q + row * PS_STR) * 4 + c16 * 16,
                 qbase + (size_t)row * QKV_N + c16 * 4);
        }
        asm volatile("cp.async.commit_group;");
        asm volatile("cp.async.wait_group 0;");
        __syncthreads();
    }
    // Q fragments, indexed by kappa(s,t,h) = 32*(s/4) + 8t + 2*(s%4) + h
    uint32_t qf[8][4];
    {
        const float* Qs = sh + SM_Q;
        const int r0 = (wid * 16 + g) * PS_STR;
#pragma unroll
        for (int s = 0; s < 8; s++) {
            int k0 = 32 * (s >> 2) + 8 * t + 2 * (s & 3);
            qf[s][0] = __float_as_uint(Qs[r0 + k0] * 0.125f);
            qf[s][1] = __float_as_uint(Qs[r0 + 8 * PS_STR + k0] * 0.125f);
            qf[s][2] = __float_as_uint(Qs[r0 + k0 + 1] * 0.125f);
            qf[s][3] = __float_as_uint(Qs[r0 + 8 * PS_STR + k0 + 1] * 0.125f);
        }
    }
    __syncthreads();

    float oacc[8][4];
#pragma unroll
    for (int nt = 0; nt < 8; nt++)
#pragma unroll
        for (int i = 0; i < 4; i++) oacc[nt][i] = 0.0f;
    float m0 = -CUDART_INF_F, m1 = -CUDART_INF_F, l0 = 0.0f, l1 = 0.0f;

    auto load_kv = [&](int kt2, int p) {
        const float* kb = qkv + rowbase + (size_t)(kt2 * KTL) * QKV_N + EMB + h * HDIM;
        const float* vb = kb + EMB;
        uint32_t kdst = sb + (p ? SM_K1 : SM_K0) * 4;
        uint32_t vdst = sb + (p ? SM_V1 : SM_V0) * 4;
#pragma unroll
        for (int i = 0; i < 4; i++) {
            int c = tid + 256 * i;              // 1024 float4 chunks each
            int row = c >> 4, c16 = c & 15;
            cp16(kdst + row * (KS_STR * 4) + c16 * 16, kb + (size_t)row * QKV_N + c16 * 4);
            cp16(vdst + row * (VS_STR * 4) + c16 * 16, vb + (size_t)row * QKV_N + c16 * 4);
        }
        asm volatile("cp.async.commit_group;");
    };

    load_kv(0, 0);
    load_kv(1, 1);

    for (int kt = 0; kt < SEQ / KTL; kt++) {
        const int p = kt & 1;
        asm volatile("cp.async.wait_group 1;");
        __syncthreads();
        const float* Ks = sh + (p ? SM_K1 : SM_K0);
        const float* Vs = sh + (p ? SM_V1 : SM_V0);

        // S = Q @ K^T  — K frags vectorized (LDS.128), nt in groups of 4
        float sacc[8][4];
#pragma unroll
        for (int nt = 0; nt < 8; nt++)
#pragma unroll
            for (int i = 0; i < 4; i++) sacc[nt][i] = 0.0f;
#pragma unroll
        for (int blk = 0; blk < 2; blk++)
#pragma unroll
        for (int hf = 0; hf < 2; hf++) {
            const int kc = 32 * blk + 8 * t + 4 * hf;
#pragma unroll
            for (int ng = 0; ng < 2; ng++) {
                float4 kv[4];
#pragma unroll
                for (int n4 = 0; n4 < 4; n4++)
                    kv[n4] = *(const float4*)&Ks[((ng * 4 + n4) * 8 + g) * KS_STR + kc];
#pragma unroll
                for (int sh2 = 0; sh2 < 2; sh2++) {
                    const int s = 4 * blk + 2 * hf + sh2;
#pragma unroll
                    for (int n4 = 0; n4 < 4; n4++) {
                        const float* be = (const float*)&kv[n4];
                        uint32_t bfrag[2];
                        bfrag[0] = __float_as_uint(be[2 * sh2]);
                        bfrag[1] = __float_as_uint(be[2 * sh2 + 1]);
                        mma_tf32(sacc[ng * 4 + n4], qf[s], bfrag);
                    }
                }
            }
        }

        // running max (rows g and g+8 of this warp's block)
        float mt0 = -CUDART_INF_F, mt1 = -CUDART_INF_F;
#pragma unroll
        for (int nt = 0; nt < 8; nt++) {
            mt0 = fmaxf(mt0, fmaxf(sacc[nt][0], sacc[nt][1]));
            mt1 = fmaxf(mt1, fmaxf(sacc[nt][2], sacc[nt][3]));
        }
        mt0 = fmaxf(mt0, __shfl_xor_sync(0xffffffffu, mt0, 1));
        mt0 = fmaxf(mt0, __shfl_xor_sync(0xffffffffu, mt0, 2));
        mt1 = fmaxf(mt1, __shfl_xor_sync(0xffffffffu, mt1, 1));
        mt1 = fmaxf(mt1, __shfl_xor_sync(0xffffffffu, mt1, 2));

        const float mn0 = fmaxf(m0, mt0), mn1 = fmaxf(m1, mt1);
        const float al0 = __expf(m0 - mn0), al1 = __expf(m1 - mn1);
        m0 = mn0; m1 = mn1;

        // rescale O by alpha (must precede PV accumulation)
#pragma unroll
        for (int nt = 0; nt < 8; nt++) {
            oacc[nt][0] *= al0; oacc[nt][1] *= al0;
            oacc[nt][2] *= al1; oacc[nt][3] *= al1;
        }

        // FUSED softmax + PV: per step nt, exp its 4 scores then immediately
        // issue the 8 PV mmas (step nt consumes keys {8nt+2t, 8nt+2t+1}).
        float s0 = 0.0f, s1 = 0.0f;
#pragma unroll
        for (int nt = 0; nt < 8; nt++) {
            float p00 = __expf(sacc[nt][0] - mn0);
            float p01 = __expf(sacc[nt][1] - mn0);
            float p10 = __expf(sacc[nt][2] - mn1);
            float p11 = __expf(sacc[nt][3] - mn1);
            s0 += p00 + p01;
            s1 += p10 + p11;
            uint32_t a[4];
            a[0] = rna_tf32_u(p00);   // P[g][k0]
            a[1] = rna_tf32_u(p10);   // P[g+8][k0]
            a[2] = rna_tf32_u(p01);   // P[g][k1]
            a[3] = rna_tf32_u(p11);   // P[g+8][k1]
            const int k0 = (8 * nt + 2 * t) * VS_STR;
#pragma unroll
            for (int ot = 0; ot < 8; ot++) {
                uint32_t bb[2];
                bb[0] = __float_as_uint(Vs[k0 + ot * 8 + g]);
                bb[1] = __float_as_uint(Vs[k0 + VS_STR + ot * 8 + g]);
                mma_tf32(oacc[ot], a, bb);
            }
        }
        // l-sum reduction overlaps with tensor-pipe drain
        s0 += __shfl_xor_sync(0xffffffffu, s0, 1);
        s0 += __shfl_xor_sync(0xffffffffu, s0, 2);
        s1 += __shfl_xor_sync(0xffffffffu, s1, 1);
        s1 += __shfl_xor_sync(0xffffffffu, s1, 2);
        l0 = l0 * al0 + s0;
        l1 = l1 * al1 + s1;

        __syncthreads();   // everyone done with buffer p
        if (kt + 2 < SEQ / KTL) load_kv(kt + 2, p);
        else asm volatile("cp.async.commit_group;");
    }

    // epilogue: normalize, rna-round (feeds tf32 out-projection), write [B,S,E]
    const float inv0 = 1.0f / l0, inv1 = 1.0f / l1;
    float* orow0 = out + (size_t)(b * SEQ + q0 + wid * 16 + g) * EMB + h * HDIM;
    float* orow1 = orow0 + (size_t)8 * EMB;
#pragma unroll
    for (int nt = 0; nt < 8; nt++) {
        const int col = nt * 8 + 2 * t;
        float2 v0 = { rna_tf32(oacc[nt][0] * inv0), rna_tf32(oacc[nt][1] * inv0) };
        float2 v1 = { rna_tf32(oacc[nt][2] * inv1), rna_tf32(oacc[nt][3] * inv1) };
        *(float2*)&orow0[col] = v0;
        *(float2*)&orow1[col] = v1;
    }
}

// ---------------------------------------------------------------------------
// launch
// ---------------------------------------------------------------------------
extern "C" void kernel_launch(void* const* d_in, const int* in_sizes, int n_in,
                              void* d_out, int out_size)
{
    const float* x     = (const float*)d_in[0];  // [2,2048,1024]
    const float* W_qkv = (const float*)d_in[1];  // [1024,3072]
    const float* b_qkv = (const float*)d_in[2];  // [3072]
    const float* W_out = (const float*)d_in[3];  // [1024,1024]
    const float* b_out = (const float*)d_in[4];  // [1024]
    float* out = (float*)d_out;                  // [2,2048,1024]

    float *qkv, *attn, *xc, *wqt, *wot;
    cudaGetSymbolAddress((void**)&qkv,  g_qkv);
    cudaGetSymbolAddress((void**)&attn, g_attn);
    cudaGetSymbolAddress((void**)&xc,   g_xc);
    cudaGetSymbolAddress((void**)&wqt,  g_wqt);
    cudaGetSymbolAddress((void**)&wot,  g_wot);

    // 0) prep: tf32-rna rounding of x, transposed+rounded weights
    cvt_rna_kernel<<<(ROWS * EMB / 4 + 255) / 256, 256>>>((const float4*)x, (float4*)xc, ROWS * EMB / 4);
    transpose_cvt_kernel<<<dim3(QKV_N / 32, EMB / 32), dim3(32, 8)>>>(W_qkv, wqt, EMB, QKV_N);
    transpose_cvt_kernel<<<dim3(EMB / 32, EMB / 32), dim3(32, 8)>>>(W_out, wot, EMB, EMB);

    cudaFuncSetAttribute(gemm_tc_kernel<true>,
                         cudaFuncAttributeMaxDynamicSharedMemorySize, GK_DSMEM);
    cudaFuncSetAttribute(gemm_tc_kernel<false>,
                         cudaFuncAttributeMaxDynamicSharedMemorySize, GK_DSMEM);
    cudaFuncSetAttribute(attn_tc_kernel,
                         cudaFuncAttributeMaxDynamicSharedMemorySize, ATTN_SMEM_BYTES);

    // 1) QKV projection (rounded output -> q,k,v are tf32 patterns)
    gemm_tc_kernel<true><<<dim3(QKV_N / 128, ROWS / 128), 256, GK_DSMEM>>>(
        xc, wqt, b_qkv, qkv, EMB, QKV_N);

    // 2) tensor-core flash attention (fused softmax+PV)
    attn_tc_kernel<<<dim3(SEQ / 128, NHEAD, BSZ), 256, ATTN_SMEM_BYTES>>>(qkv, attn);

    // 3) output projection (exact fp32 output)
    gemm_tc_kernel<false><<<dim3(EMB / 128, ROWS / 128), 256, GK_DSMEM>>>(
        attn, wot, b_out, out, EMB, EMB);
}

// round 12
// speedup vs baseline: 1.0560x; 1.0557x over previous
#include <cuda_runtime.h>
#include <cuda_bf16.h>
#include <math_constants.h>
#include <cstdint>

// Problem constants (fixed by reference): B=2, S=2048, E=1024, H=16, D=64
#define BSZ   2
#define SEQ   2048
#define EMB   1024
#define NHEAD 16
#define HDIM  64
#define ROWS  (BSZ * SEQ)          // 4096
#define QKV_N (3 * EMB)            // 3072

// Scratch (allocation-free rule: __device__ globals)
static __device__ float g_qkv[ROWS * QKV_N];    // [4096, 3072] (tf32-rounded)
static __device__ float g_attn[ROWS * EMB];     // [4096, 1024] (tf32-rounded)
static __device__ float g_xc[ROWS * EMB];       // x, tf32-rounded
static __device__ float g_wqt[QKV_N * EMB];     // W_qkv^T [3072,1024], tf32-rounded
static __device__ float g_wot[EMB * EMB];       // W_out^T [1024,1024], tf32-rounded

// ---------------------------------------------------------------------------
// helpers
// ---------------------------------------------------------------------------
__device__ __forceinline__ uint32_t smem_to_u32(const void* p) {
    uint32_t a;
    asm("{ .reg .u64 t; cvta.to.shared.u64 t, %1; cvt.u32.u64 %0, t; }" : "=r"(a) : "l"(p));
    return a;
}
// cvt.rna.tf32.f32 writes a .b32 destination (tf32 is a bit pattern)
__device__ __forceinline__ float rna_tf32(float x) {
    uint32_t r;
    asm("cvt.rna.tf32.f32 %0, %1;" : "=r"(r) : "f"(x));
    return __uint_as_float(r);
}
__device__ __forceinline__ uint32_t rna_tf32_u(float x) {
    uint32_t r;
    asm("cvt.rna.tf32.f32 %0, %1;" : "=r"(r) : "f"(x));
    return r;
}
__device__ __forceinline__ void cp16(uint32_t d, const void* s) {
    asm volatile("cp.async.cg.shared.global [%0], [%1], 16;" :: "r"(d), "l"(s));
}
// warp-level tf32 MMA (sm_80+; works at compute_100)
__device__ __forceinline__ void mma_tf32(float* c, const uint32_t* a, const uint32_t* b) {
    asm volatile("mma.sync.aligned.m16n8k8.row.col.f32.tf32.tf32.f32 "
                 "{%0,%1,%2,%3}, {%4,%5,%6,%7}, {%8,%9}, {%0,%1,%2,%3};"
                 : "+f"(c[0]), "+f"(c[1]), "+f"(c[2]), "+f"(c[3])
                 : "r"(a[0]), "r"(a[1]), "r"(a[2]), "r"(a[3]),
                   "r"(b[0]), "r"(b[1]));
}

// ---------------------------------------------------------------------------
// Prep kernels: tf32-rna rounding (+ transpose for weights)
// ---------------------------------------------------------------------------
__global__ void cvt_rna_kernel(const float4* __restrict__ in, float4* __restrict__ out, int n4) {
    int i = blockIdx.x * blockDim.x + threadIdx.x;
    if (i < n4) {
        float4 v = in[i];
        v.x = rna_tf32(v.x); v.y = rna_tf32(v.y);
        v.z = rna_tf32(v.z); v.w = rna_tf32(v.w);
        out[i] = v;
    }
}

// in: [R,C] row-major  ->  out: [C,R] row-major, rna-rounded
__global__ void transpose_cvt_kernel(const float* __restrict__ in, float* __restrict__ out,
                                     int R, int C) {
    __shared__ float t[32][33];
    int c0 = blockIdx.x * 32, r0 = blockIdx.y * 32;
    int tx = threadIdx.x, ty = threadIdx.y;
#pragma unroll
    for (int i = 0; i < 32; i += 8)
        t[ty + i][tx] = in[(size_t)(r0 + ty + i) * C + c0 + tx];
    __syncthreads();
#pragma unroll
    for (int i = 0; i < 32; i += 8)
        out[(size_t)(c0 + ty + i) * R + r0 + tx] = rna_tf32(t[tx][ty + i]);
}

// ---------------------------------------------------------------------------
// tf32 warp-MMA GEMM + bias: C[M,N] = A[M,K] @ Bt[N,K]^T + bias[N]
// CTA tile 128x128, 4 warps (2x2), each warp 64x64 (4x8 m16n8k8 tiles).
// Bigger warp tile = operand reuse: 32 LDS feed 32 mmas per k8 step
// (was 24 LDS / 16 mmas), cutting smem bytes/FLOP by 1.5x — the smem
// crossbar (128 B/cyc/SM) was the binding constraint.
// ROUND: rna-round the output (for tensors feeding later tf32 MMAs).
// ---------------------------------------------------------------------------
#define RS        36                       // smem row stride in floats
#define ASTG      (128 * RS)               // words per operand stage (4608)
#define STG_WORDS (2 * ASTG)               // A + B per stage (9216)
#define GK_DSMEM  (2 * STG_WORDS * 4)      // 73728 B

template <bool ROUND>
__global__ void __launch_bounds__(128, 2)
gemm_tc_kernel(const float* __restrict__ A, const float* __restrict__ Bt,
               const float* __restrict__ bias, float* __restrict__ C,
               int K, int N)
{
    extern __shared__ float sh[];
    const int tid = threadIdx.x;
    const int wid = tid >> 5, lane = tid & 31;
    const int g = lane >> 2, t = lane & 3;
    const int row0 = blockIdx.y * 128;
    const int col0 = blockIdx.x * 128;
    const int mbase = (wid & 1) * 64;
    const int nbase = (wid >> 1) * 64;
    const int NK = K / 32;
    const uint32_t sb = smem_to_u32(sh);

    auto load_stage = [&](int j, int p) {
        const float* Ab = A + (size_t)row0 * K + j * 32;
        const float* Bb = Bt + (size_t)col0 * K + j * 32;
        uint32_t abase = sb + p * (STG_WORDS * 4);
        uint32_t bbase = abase + ASTG * 4;
#pragma unroll
        for (int i = 0; i < 8; i++) {
            int c = tid + 128 * i;
            int row = c >> 3, c8 = c & 7;
            cp16(abase + row * (RS * 4) + c8 * 16, Ab + (size_t)row * K + c8 * 4);
            cp16(bbase + row * (RS * 4) + c8 * 16, Bb + (size_t)row * K + c8 * 4);
        }
        asm volatile("cp.async.commit_group;");
    };

    float acc[4][8][4];
#pragma unroll
    for (int mt = 0; mt < 4; mt++)
#pragma unroll
        for (int nt = 0; nt < 8; nt++)
#pragma unroll
            for (int i = 0; i < 4; i++) acc[mt][nt][i] = 0.0f;

    load_stage(0, 0);
    load_stage(1, 1);

    for (int j = 0; j < NK; j++) {
        const int p = j & 1;
        asm volatile("cp.async.wait_group 1;");
        __syncthreads();

        const float* As = sh + p * STG_WORDS;
        const float* Bs = As + ASTG;
#pragma unroll
        for (int ks = 0; ks < 4; ks++) {
            const int kc = ks * 8;
            uint32_t a[4][4];
#pragma unroll
            for (int mt = 0; mt < 4; mt++) {
                int r0 = (mbase + mt * 16 + g) * RS + kc + t;
                a[mt][0] = __float_as_uint(As[r0]);
                a[mt][1] = __float_as_uint(As[r0 + 8 * RS]);
                a[mt][2] = __float_as_uint(As[r0 + 4]);
                a[mt][3] = __float_as_uint(As[r0 + 8 * RS + 4]);
            }
#pragma unroll
            for (int nt = 0; nt < 8; nt++) {
                int r0 = (nbase + nt * 8 + g) * RS + kc + t;
                uint32_t b[2];
                b[0] = __float_as_uint(Bs[r0]);
                b[1] = __float_as_uint(Bs[r0 + 4]);
#pragma unroll
                for (int mt = 0; mt < 4; mt++)
                    mma_tf32(acc[mt][nt], a[mt], b);
            }
        }
        __syncthreads();
        if (j + 2 < NK) load_stage(j + 2, p);
        else asm volatile("cp.async.commit_group;");   // keep group count in step
    }

    // epilogue: c0/c1 -> (row, col..col+1), c2/c3 -> (row+8, ...)
#pragma unroll
    for (int mt = 0; mt < 4; mt++) {
        const int row = row0 + mbase + mt * 16 + g;
#pragma unroll
        for (int nt = 0; nt < 8; nt++) {
            const int col = col0 + nbase + nt * 8 + t * 2;
            const float b0 = bias[col], b1 = bias[col + 1];
            float2 v0, v1;
            if (ROUND) {
                v0 = { rna_tf32(acc[mt][nt][0] + b0), rna_tf32(acc[mt][nt][1] + b1) };
                v1 = { rna_tf32(acc[mt][nt][2] + b0), rna_tf32(acc[mt][nt][3] + b1) };
            } else {
                v0 = { acc[mt][nt][0] + b0, acc[mt][nt][1] + b1 };
                v1 = { acc[mt][nt][2] + b0, acc[mt][nt][3] + b1 };
            }
            *(float2*)&C[(size_t)row * N + col] = v0;
            *(float2*)&C[(size_t)(row + 8) * N + col] = v1;
        }
    }
}

// ---------------------------------------------------------------------------
// Tensor-core flash attention (non-causal, sm_scale = 1/8).
// CTA: 128 q-rows x one head; 4 warps, each owns 32 q-rows (2 m-tiles);
// 2 CTAs/SM. K-tile 64 keys, cp.async double-buffered.
// 2 m-tiles/warp = operand reuse: every K and V fragment read from smem
// feeds TWO mmas, halving smem bytes/FLOP (crossbar was saturated at
// 128 B/cyc with 1 m-tile/warp — the round-10/11 null results).
// QK^T: K-frags LDS.128 via k-remap kappa(s,t,h)=32(s/4)+8t+2(s%4)+h.
// P.V:  register-direct P (step s = softmax output sacc[.][s]), fused
//       exp->mma per step; V row-major VS_STR=68 conflict-free.
// ---------------------------------------------------------------------------
#define KTL    64
#define KS_STR 68
#define VS_STR 68
#define PS_STR 68
#define SM_K0  0
#define SM_K1  (64 * KS_STR)
#define SM_V0  (2 * 64 * KS_STR)
#define SM_V1  (SM_V0 + 64 * VS_STR)
#define SM_Q   (SM_V0 + 2 * 64 * VS_STR)
#define ATTN_SMEM_FLOATS (SM_Q + 128 * PS_STR)
#define ATTN_SMEM_BYTES  (ATTN_SMEM_FLOATS * 4)

__global__ void __launch_bounds__(128, 2)
attn_tc_kernel(const float* __restrict__ qkv, float* __restrict__ out)
{
    extern __shared__ float sh[];
    const uint32_t sb = smem_to_u32(sh);
    const int tid = threadIdx.x, wid = tid >> 5, lane = tid & 31;
    const int g = lane >> 2, t = lane & 3;
    const int h = blockIdx.y, b = blockIdx.z;
    const int q0 = blockIdx.x * 128;
    const size_t rowbase = (size_t)(b * SEQ) * QKV_N;
    const float* qbase = qkv + rowbase + (size_t)q0 * QKV_N + h * HDIM;

    // stage Q[128,64]
    {
#pragma unroll
        for (int i = 0; i < 16; i++) {
            int c = tid + 128 * i;              // 2048 float4 chunks
            int row = c >> 4, c16 = c & 15;
            cp16(sb + (SM_Q + row * PS_STR) * 4 + c16 * 16,
                 qbase + (size_t)row * QKV_N + c16 * 4);
        }
        asm volatile("cp.async.commit_group;");
        asm volatile("cp.async.wait_group 0;");
        __syncthreads();
    }
    // Q fragments for 2 m-tiles (rows 32*wid + 16*mt + {g, g+8}),
    // k-indexed by kappa(s,t,h) = 32*(s/4) + 8t + 2*(s%4) + h
    uint32_t qf[2][8][4];
    {
        const float* Qs = sh + SM_Q;
#pragma unroll
        for (int mt = 0; mt < 2; mt++) {
            const int r0 = (wid * 32 + mt * 16 + g) * PS_STR;
#pragma unroll
            for (int s = 0; s < 8; s++) {
                int k0 = 32 * (s >> 2) + 8 * t + 2 * (s & 3);
                qf[mt][s][0] = __float_as_uint(Qs[r0 + k0] * 0.125f);
                qf[mt][s][1] = __float_as_uint(Qs[r0 + 8 * PS_STR + k0] * 0.125f);
                qf[mt][s][2] = __float_as_uint(Qs[r0 + k0 + 1] * 0.125f);
                qf[mt][s][3] = __float_as_uint(Qs[r0 + 8 * PS_STR + k0 + 1] * 0.125f);
            }
        }
    }
    __syncthreads();

    float oacc[2][8][4];
#pragma unroll
    for (int mt = 0; mt < 2; mt++)
#pragma unroll
        for (int nt = 0; nt < 8; nt++)
#pragma unroll
            for (int i = 0; i < 4; i++) oacc[mt][nt][i] = 0.0f;
    float m[2][2] = { {-CUDART_INF_F, -CUDART_INF_F}, {-CUDART_INF_F, -CUDART_INF_F} };
    float l[2][2] = { {0.0f, 0.0f}, {0.0f, 0.0f} };

    auto load_kv = [&](int kt2, int p) {
        const float* kb = qkv + rowbase + (size_t)(kt2 * KTL) * QKV_N + EMB + h * HDIM;
        const float* vb = kb + EMB;
        uint32_t kdst = sb + (p ? SM_K1 : SM_K0) * 4;
        uint32_t vdst = sb + (p ? SM_V1 : SM_V0) * 4;
#pragma unroll
        for (int i = 0; i < 8; i++) {
            int c = tid + 128 * i;              // 1024 float4 chunks each
            int row = c >> 4, c16 = c & 15;
            cp16(kdst + row * (KS_STR * 4) + c16 * 16, kb + (size_t)row * QKV_N + c16 * 4);
            cp16(vdst + row * (VS_STR * 4) + c16 * 16, vb + (size_t)row * QKV_N + c16 * 4);
        }
        asm volatile("cp.async.commit_group;");
    };

    load_kv(0, 0);
    load_kv(1, 1);

    for (int kt = 0; kt < SEQ / KTL; kt++) {
        const int p = kt & 1;
        asm volatile("cp.async.wait_group 1;");
        __syncthreads();
        const float* Ks = sh + (p ? SM_K1 : SM_K0);
        const float* Vs = sh + (p ? SM_V1 : SM_V0);

        // S = Q @ K^T — each K fragment feeds BOTH m-tiles
        float sacc[2][8][4];
#pragma unroll
        for (int mt = 0; mt < 2; mt++)
#pragma unroll
            for (int nt = 0; nt < 8; nt++)
#pragma unroll
                for (int i = 0; i < 4; i++) sacc[mt][nt][i] = 0.0f;
#pragma unroll
        for (int blk = 0; blk < 2; blk++)
#pragma unroll
        for (int hf = 0; hf < 2; hf++) {
            const int kc = 32 * blk + 8 * t + 4 * hf;
#pragma unroll
            for (int ng = 0; ng < 2; ng++) {
                float4 kv[4];
#pragma unroll
                for (int n4 = 0; n4 < 4; n4++)
                    kv[n4] = *(const float4*)&Ks[((ng * 4 + n4) * 8 + g) * KS_STR + kc];
#pragma unroll
                for (int sh2 = 0; sh2 < 2; sh2++) {
                    const int s = 4 * blk + 2 * hf + sh2;
#pragma unroll
                    for (int n4 = 0; n4 < 4; n4++) {
                        const float* be = (const float*)&kv[n4];
                        uint32_t bfrag[2];
                        bfrag[0] = __float_as_uint(be[2 * sh2]);
                        bfrag[1] = __float_as_uint(be[2 * sh2 + 1]);
                        mma_tf32(sacc[0][ng * 4 + n4], qf[0][s], bfrag);
                        mma_tf32(sacc[1][ng * 4 + n4], qf[1][s], bfrag);
                    }
                }
            }
        }

        // running max per m-tile (rows g and g+8)
        float mn[2][2], al[2][2];
#pragma unroll
        for (int mt = 0; mt < 2; mt++) {
            float mt0 = -CUDART_INF_F, mt1 = -CUDART_INF_F;
#pragma unroll
            for (int nt = 0; nt < 8; nt++) {
                mt0 = fmaxf(mt0, fmaxf(sacc[mt][nt][0], sacc[mt][nt][1]));
                mt1 = fmaxf(mt1, fmaxf(sacc[mt][nt][2], sacc[mt][nt][3]));
            }
            mt0 = fmaxf(mt0, __shfl_xor_sync(0xffffffffu, mt0, 1));
            mt0 = fmaxf(mt0, __shfl_xor_sync(0xffffffffu, mt0, 2));
            mt1 = fmaxf(mt1, __shfl_xor_sync(0xffffffffu, mt1, 1));
            mt1 = fmaxf(mt1, __shfl_xor_sync(0xffffffffu, mt1, 2));
            mn[mt][0] = fmaxf(m[mt][0], mt0);
            mn[mt][1] = fmaxf(m[mt][1], mt1);
            al[mt][0] = __expf(m[mt][0] - mn[mt][0]);
            al[mt][1] = __expf(m[mt][1] - mn[mt][1]);
            m[mt][0] = mn[mt][0];
            m[mt][1] = mn[mt][1];
            // rescale O by alpha (must precede PV accumulation)
#pragma unroll
            for (int nt = 0; nt < 8; nt++) {
                oacc[mt][nt][0] *= al[mt][0]; oacc[mt][nt][1] *= al[mt][0];
                oacc[mt][nt][2] *= al[mt][1]; oacc[mt][nt][3] *= al[mt][1];
            }
        }

        // FUSED softmax + PV: per step nt, exp both m-tiles' scores, then the
        // 8 V fragments (2 LDS each) feed 16 mmas (2 m-tiles).
        float sum[2][2] = { {0.0f, 0.0f}, {0.0f, 0.0f} };
#pragma unroll
        for (int nt = 0; nt < 8; nt++) {
            uint32_t a0[4], a1[4];
            {
                float p00 = __expf(sacc[0][nt][0] - mn[0][0]);
                float p01 = __expf(sacc[0][nt][1] - mn[0][0]);
                float p10 = __expf(sacc[0][nt][2] - mn[0][1]);
                float p11 = __expf(sacc[0][nt][3] - mn[0][1]);
                sum[0][0] += p00 + p01; sum[0][1] += p10 + p11;
                a0[0] = rna_tf32_u(p00); a0[1] = rna_tf32_u(p10);
                a0[2] = rna_tf32_u(p01); a0[3] = rna_tf32_u(p11);
            }
            {
                float p00 = __expf(sacc[1][nt][0] - mn[1][0]);
                float p01 = __expf(sacc[1][nt][1] - mn[1][0]);
                float p10 = __expf(sacc[1][nt][2] - mn[1][1]);
                float p11 = __expf(sacc[1][nt][3] - mn[1][1]);
                sum[1][0] += p00 + p01; sum[1][1] += p10 + p11;
                a1[0] = rna_tf32_u(p00); a1[1] = rna_tf32_u(p10);
                a1[2] = rna_tf32_u(p01); a1[3] = rna_tf32_u(p11);
            }
            const int k0 = (8 * nt + 2 * t) * VS_STR;
#pragma unroll
            for (int ot = 0; ot < 8; ot++) {
                uint32_t bb[2];
                bb[0] = __float_as_uint(Vs[k0 + ot * 8 + g]);
                bb[1] = __float_as_uint(Vs[k0 + VS_STR + ot * 8 + g]);
                mma_tf32(oacc[0][ot], a0, bb);
                mma_tf32(oacc[1][ot], a1, bb);
            }
        }
        // l-sum reductions overlap with tensor-pipe drain
#pragma unroll
        for (int mt = 0; mt < 2; mt++) {
            float s0 = sum[mt][0], s1 = sum[mt][1];
            s0 += __shfl_xor_sync(0xffffffffu, s0, 1);
            s0 += __shfl_xor_sync(0xffffffffu, s0, 2);
            s1 += __shfl_xor_sync(0xffffffffu, s1, 1);
            s1 += __shfl_xor_sync(0xffffffffu, s1, 2);
            l[mt][0] = l[mt][0] * al[mt][0] + s0;
            l[mt][1] = l[mt][1] * al[mt][1] + s1;
        }

        __syncthreads();   // everyone done with buffer p
        if (kt + 2 < SEQ / KTL) load_kv(kt + 2, p);
        else asm volatile("cp.async.commit_group;");
    }

    // epilogue: normalize, rna-round (feeds tf32 out-projection), write [B,S,E]
#pragma unroll
    for (int mt = 0; mt < 2; mt++) {
        const float inv0 = 1.0f / l[mt][0], inv1 = 1.0f / l[mt][1];
        float* orow0 = out + (size_t)(b * SEQ + q0 + wid * 32 + mt * 16 + g) * EMB + h * HDIM;
        float* orow1 = orow0 + (size_t)8 * EMB;
#pragma unroll
        for (int nt = 0; nt < 8; nt++) {
            const int col = nt * 8 + 2 * t;
            float2 v0 = { rna_tf32(oacc[mt][nt][0] * inv0), rna_tf32(oacc[mt][nt][1] * inv0) };
            float2 v1 = { rna_tf32(oacc[mt][nt][2] * inv1), rna_tf32(oacc[mt][nt][3] * inv1) };
            *(float2*)&orow0[col] = v0;
            *(float2*)&orow1[col] = v1;
        }
    }
}

// ---------------------------------------------------------------------------
// launch
// ---------------------------------------------------------------------------
extern "C" void kernel_launch(void* const* d_in, const int* in_sizes, int n_in,
                              void* d_out, int out_size)
{
    const float* x     = (const float*)d_in[0];  // [2,2048,1024]
    const float* W_qkv = (const float*)d_in[1];  // [1024,3072]
    const float* b_qkv = (const float*)d_in[2];  // [3072]
    const float* W_out = (const float*)d_in[3];  // [1024,1024]
    const float* b_out = (const float*)d_in[4];  // [1024]
    float* out = (float*)d_out;                  // [2,2048,1024]

    float *qkv, *attn, *xc, *wqt, *wot;
    cudaGetSymbolAddress((void**)&qkv,  g_qkv);
    cudaGetSymbolAddress((void**)&attn, g_attn);
    cudaGetSymbolAddress((void**)&xc,   g_xc);
    cudaGetSymbolAddress((void**)&wqt,  g_wqt);
    cudaGetSymbolAddress((void**)&wot,  g_wot);

    // 0) prep: tf32-rna rounding of x, transposed+rounded weights
    cvt_rna_kernel<<<(ROWS * EMB / 4 + 255) / 256, 256>>>((const float4*)x, (float4*)xc, ROWS * EMB / 4);
    transpose_cvt_kernel<<<dim3(QKV_N / 32, EMB / 32), dim3(32, 8)>>>(W_qkv, wqt, EMB, QKV_N);
    transpose_cvt_kernel<<<dim3(EMB / 32, EMB / 32), dim3(32, 8)>>>(W_out, wot, EMB, EMB);

    cudaFuncSetAttribute(gemm_tc_kernel<true>,
                         cudaFuncAttributeMaxDynamicSharedMemorySize, GK_DSMEM);
    cudaFuncSetAttribute(gemm_tc_kernel<false>,
                         cudaFuncAttributeMaxDynamicSharedMemorySize, GK_DSMEM);
    cudaFuncSetAttribute(attn_tc_kernel,
                         cudaFuncAttributeMaxDynamicSharedMemorySize, ATTN_SMEM_BYTES);

    // 1) QKV projection (rounded output -> q,k,v are tf32 patterns)
    gemm_tc_kernel<true><<<dim3(QKV_N / 128, ROWS / 128), 128, GK_DSMEM>>>(
        xc, wqt, b_qkv, qkv, EMB, QKV_N);

    // 2) tensor-core flash attention (2 m-tiles/warp, fused softmax+PV)
    attn_tc_kernel<<<dim3(SEQ / 128, NHEAD, BSZ), 128, ATTN_SMEM_BYTES>>>(qkv, attn);

    // 3) output projection (exact fp32 output)
    gemm_tc_kernel<false><<<dim3(EMB / 128, ROWS / 128), 128, GK_DSMEM>>>(
        attn, wot, b_out, out, EMB, EMB);
}

// round 13
// speedup vs baseline: 1.8730x; 1.7736x over previous
#include <cuda_runtime.h>
#include <cuda_fp16.h>
#include <math_constants.h>
#include <cstdint>

// Problem constants (fixed by reference): B=2, S=2048, E=1024, H=16, D=64
#define BSZ   2
#define SEQ   2048
#define EMB   1024
#define NHEAD 16
#define HDIM  64
#define ROWS  (BSZ * SEQ)          // 4096
#define QKV_N (3 * EMB)            // 3072

// Scratch (allocation-free rule: __device__ globals). All tensor-core inputs
// live as fp16 (same 11-bit mantissa as tf32 -> same rounding error budget).
static __device__ __half g_qkvh[ROWS * QKV_N];   // QKV projection output
static __device__ __half g_attnh[ROWS * EMB];    // attention output
static __device__ __half g_xh[ROWS * EMB];       // x, fp16
static __device__ __half g_wqth[QKV_N * EMB];    // W_qkv^T [3072,1024]
static __device__ __half g_woth[EMB * EMB];      // W_out^T [1024,1024]
static __device__ __half g_vth[BSZ * NHEAD * HDIM * SEQ];  // per-head V^T [b][h][d][s]

// ---------------------------------------------------------------------------
// helpers
// ---------------------------------------------------------------------------
__device__ __forceinline__ uint32_t smem_to_u32(const void* p) {
    uint32_t a;
    asm("{ .reg .u64 t; cvta.to.shared.u64 t, %1; cvt.u32.u64 %0, t; }" : "=r"(a) : "l"(p));
    return a;
}
__device__ __forceinline__ void cp16(uint32_t d, const void* s) {
    asm volatile("cp.async.cg.shared.global [%0], [%1], 16;" :: "r"(d), "l"(s));
}
// fp16 warp MMA, fp32 accumulate (sm_80+; works at compute_100)
__device__ __forceinline__ void mma_f16(float* c, const uint32_t* a, const uint32_t* b) {
    asm volatile("mma.sync.aligned.m16n8k16.row.col.f32.f16.f16.f32 "
                 "{%0,%1,%2,%3}, {%4,%5,%6,%7}, {%8,%9}, {%0,%1,%2,%3};"
                 : "+f"(c[0]), "+f"(c[1]), "+f"(c[2]), "+f"(c[3])
                 : "r"(a[0]), "r"(a[1]), "r"(a[2]), "r"(a[3]),
                   "r"(b[0]), "r"(b[1]));
}
__device__ __forceinline__ uint32_t pack_h2(float x, float y) {
    __half2 h = __floats2half2_rn(x, y);
    return *(uint32_t*)&h;
}

// ---------------------------------------------------------------------------
// Prep kernels: fp32 -> fp16 (+ transpose for weights)
// ---------------------------------------------------------------------------
__global__ void f2h_kernel(const float4* __restrict__ in, __half2* __restrict__ out, int n4) {
    int i = blockIdx.x * blockDim.x + threadIdx.x;
    if (i < n4) {
        float4 v = in[i];
        out[2 * i]     = __floats2half2_rn(v.x, v.y);
        out[2 * i + 1] = __floats2half2_rn(v.z, v.w);
    }
}

// in: [R,C] fp32 row-major -> out: [C,R] fp16 row-major
__global__ void transpose_h_kernel(const float* __restrict__ in, __half* __restrict__ out,
                                   int R, int C) {
    __shared__ float t[32][33];
    int c0 = blockIdx.x * 32, r0 = blockIdx.y * 32;
    int tx = threadIdx.x, ty = threadIdx.y;
#pragma unroll
    for (int i = 0; i < 32; i += 8)
        t[ty + i][tx] = in[(size_t)(r0 + ty + i) * C + c0 + tx];
    __syncthreads();
#pragma unroll
    for (int i = 0; i < 32; i += 8)
        out[(size_t)(c0 + ty + i) * R + r0 + tx] = __float2half_rn(t[tx][ty + i]);
}

// Per-head V transpose: g_qkvh V slab [b*S+s][2048+h*64+d] -> g_vth[(b,h,d)][s]
__global__ void vth_transpose_kernel(const __half* __restrict__ qkv, __half* __restrict__ vt) {
    __shared__ __half t[32][33];
    const int bh = blockIdx.z;            // b*16 + h
    const int b = bh >> 4, h = bh & 15;
    const int s0 = blockIdx.x * 32, d0 = blockIdx.y * 32;
    const int tx = threadIdx.x, ty = threadIdx.y;
    const __half* in = qkv + (size_t)(b * SEQ) * QKV_N + 2 * EMB + h * HDIM;
#pragma unroll
    for (int i = 0; i < 32; i += 8)
        t[ty + i][tx] = in[(size_t)(s0 + ty + i) * QKV_N + d0 + tx];
    __syncthreads();
    __half* outp = vt + ((size_t)bh * HDIM + d0) * SEQ + s0;
#pragma unroll
    for (int i = 0; i < 32; i += 8)
        outp[(size_t)(ty + i) * SEQ + tx] = t[tx][ty + i];
}

// ---------------------------------------------------------------------------
// fp16 warp-MMA GEMM + bias: C[M,N] = A[M,K] @ Bt[N,K]^T + bias[N]
// CTA tile 128x128, 4 warps (2x2), warp 64x64 (4x8 m16n8k16 tiles).
// K-stage 64 halves, cp.async double buffer, smem stride 72 halves (144B):
// fragment u32 loads hit banks (4g+t [+4]) mod 32 — conflict-free.
// OUTH: write fp16 (feeds later fp16 MMAs) vs fp32 (final output).
// ---------------------------------------------------------------------------
#define RS_H    72                          // smem row stride in halves
#define ASTG_H  (128 * RS_H)                // halves per operand stage (9216)
#define STG_H   (2 * ASTG_H)                // A + B per stage (18432 halves)
#define GK_DSMEM (2 * STG_H * 2)            // 73728 B

template <bool OUTH>
__global__ void __launch_bounds__(128, 2)
gemm_h_kernel(const __half* __restrict__ A, const __half* __restrict__ Bt,
              const float* __restrict__ bias, void* __restrict__ Cv,
              int K, int N)
{
    extern __shared__ __half shh[];
    const int tid = threadIdx.x;
    const int wid = tid >> 5, lane = tid & 31;
    const int g = lane >> 2, t = lane & 3;
    const int row0 = blockIdx.y * 128;
    const int col0 = blockIdx.x * 128;
    const int mbase = (wid & 1) * 64;
    const int nbase = (wid >> 1) * 64;
    const int NK = K / 64;
    const uint32_t sb = smem_to_u32(shh);

    auto load_stage = [&](int j, int p) {
        const __half* Ab = A + (size_t)row0 * K + j * 64;
        const __half* Bb = Bt + (size_t)col0 * K + j * 64;
        uint32_t abase = sb + p * (STG_H * 2);
        uint32_t bbase = abase + ASTG_H * 2;
#pragma unroll
        for (int i = 0; i < 8; i++) {
            int c = tid + 128 * i;            // 1024 chunks each (128 rows x 8)
            int row = c >> 3, c8 = c & 7;
            cp16(abase + row * (RS_H * 2) + c8 * 16, Ab + (size_t)row * K + c8 * 8);
            cp16(bbase + row * (RS_H * 2) + c8 * 16, Bb + (size_t)row * K + c8 * 8);
        }
        asm volatile("cp.async.commit_group;");
    };

    float acc[4][8][4];
#pragma unroll
    for (int mt = 0; mt < 4; mt++)
#pragma unroll
        for (int nt = 0; nt < 8; nt++)
#pragma unroll
            for (int i = 0; i < 4; i++) acc[mt][nt][i] = 0.0f;

    load_stage(0, 0);
    load_stage(1, 1);

    for (int j = 0; j < NK; j++) {
        const int p = j & 1;
        asm volatile("cp.async.wait_group 1;");
        __syncthreads();

        const __half* As = shh + p * STG_H;
        const __half* Bs = As + ASTG_H;
#pragma unroll
        for (int ks = 0; ks < 4; ks++) {
            const int kc = ks * 16;
            uint32_t a[4][4];
#pragma unroll
            for (int mt = 0; mt < 4; mt++) {
                int r0 = (mbase + mt * 16 + g) * RS_H + kc + 2 * t;
                a[mt][0] = *(const uint32_t*)&As[r0];
                a[mt][1] = *(const uint32_t*)&As[r0 + 8 * RS_H];
                a[mt][2] = *(const uint32_t*)&As[r0 + 8];
                a[mt][3] = *(const uint32_t*)&As[r0 + 8 * RS_H + 8];
            }
#pragma unroll
            for (int nt = 0; nt < 8; nt++) {
                int r0 = (nbase + nt * 8 + g) * RS_H + kc + 2 * t;
                uint32_t b[2];
                b[0] = *(const uint32_t*)&Bs[r0];
                b[1] = *(const uint32_t*)&Bs[r0 + 8];
#pragma unroll
                for (int mt = 0; mt < 4; mt++)
                    mma_f16(acc[mt][nt], a[mt], b);
            }
        }
        __syncthreads();
        if (j + 2 < NK) load_stage(j + 2, p);
        else asm volatile("cp.async.commit_group;");   // keep group count in step
    }

    // epilogue: c0/c1 -> (row, col..col+1), c2/c3 -> (row+8, ...)
#pragma unroll
    for (int mt = 0; mt < 4; mt++) {
        const int row = row0 + mbase + mt * 16 + g;
#pragma unroll
        for (int nt = 0; nt < 8; nt++) {
            const int col = col0 + nbase + nt * 8 + t * 2;
            const float b0 = bias[col], b1 = bias[col + 1];
            if (OUTH) {
                __half* C = (__half*)Cv;
                *(__half2*)&C[(size_t)row * N + col] =
                    __floats2half2_rn(acc[mt][nt][0] + b0, acc[mt][nt][1] + b1);
                *(__half2*)&C[(size_t)(row + 8) * N + col] =
                    __floats2half2_rn(acc[mt][nt][2] + b0, acc[mt][nt][3] + b1);
            } else {
                float* C = (float*)Cv;
                float2 v0 = { acc[mt][nt][0] + b0, acc[mt][nt][1] + b1 };
                float2 v1 = { acc[mt][nt][2] + b0, acc[mt][nt][3] + b1 };
                *(float2*)&C[(size_t)row * N + col] = v0;
                *(float2*)&C[(size_t)(row + 8) * N + col] = v1;
            }
        }
    }
}

// ---------------------------------------------------------------------------
// fp16 tensor-core flash attention (non-causal, sm_scale = 1/8 folded into
// the softmax exp as an exact fma — no q prescale).
// CTA: 128 q-rows x one head; 4 warps x 2 m-tiles; 2 CTAs/SM.
// K-tile 64 keys. K staged keys x dims (QK^T B-frags = u32 pairs);
// V staged TRANSPOSED (dims x keys, from g_vth) so PV B-frags are u32 pairs.
// P stays in registers packed to half2 (register-direct PV, fused with exp).
// Strides 72 halves: all fragment access patterns bank-conflict-free.
// ---------------------------------------------------------------------------
#define KTL    64
#define AS_H   72                         // stride (halves) for K, V^T, Q tiles
#define SM_K0  0
#define SM_K1  (64 * AS_H)                // 4608
#define SM_V0  (2 * 64 * AS_H)            // 9216
#define SM_V1  (SM_V0 + 64 * AS_H)
#define SM_Q   (SM_V0 + 2 * 64 * AS_H)    // 18432
#define ATTN_SMEM_HALVES (SM_Q + 128 * AS_H)
#define ATTN_SMEM_BYTES  (ATTN_SMEM_HALVES * 2)   // 55296 B

__global__ void __launch_bounds__(128, 2)
attn_tc_kernel(const __half* __restrict__ qkv, const __half* __restrict__ vt,
               __half* __restrict__ out)
{
    extern __shared__ __half shh[];
    const uint32_t sb = smem_to_u32(shh);
    const int tid = threadIdx.x, wid = tid >> 5, lane = tid & 31;
    const int g = lane >> 2, t = lane & 3;
    const int h = blockIdx.y, b = blockIdx.z;
    const int q0 = blockIdx.x * 128;
    const size_t rowbase = (size_t)(b * SEQ) * QKV_N;
    const __half* qbase = qkv + rowbase + (size_t)q0 * QKV_N + h * HDIM;
    const __half* vtbase = vt + ((size_t)((b * NHEAD + h) * HDIM)) * SEQ;

    // stage Q[128 rows x 64 halves]
    {
#pragma unroll
        for (int i = 0; i < 8; i++) {
            int c = tid + 128 * i;            // 1024 chunks (128 rows x 8)
            int row = c >> 3, c8 = c & 7;
            cp16(sb + (SM_Q + row * AS_H) * 2 + c8 * 16,
                 qbase + (size_t)row * QKV_N + c8 * 8);
        }
        asm volatile("cp.async.commit_group;");
        asm volatile("cp.async.wait_group 0;");
        __syncthreads();
    }
    // Q fragments: m16n8k16 A layout — a0=(row g, k 2t..2t+1), a1=(row g+8),
    // a2=(row g, k 8+2t), a3=(row g+8, k 8+2t); 4 k16 steps cover d=64.
    uint32_t qf[2][4][4];
    {
        const __half* Qs = shh + SM_Q;
#pragma unroll
        for (int mt = 0; mt < 2; mt++) {
            const int r0 = (wid * 32 + mt * 16 + g) * AS_H;
#pragma unroll
            for (int s = 0; s < 4; s++) {
                int k0 = r0 + 16 * s + 2 * t;
                qf[mt][s][0] = *(const uint32_t*)&Qs[k0];
                qf[mt][s][1] = *(const uint32_t*)&Qs[k0 + 8 * AS_H];
                qf[mt][s][2] = *(const uint32_t*)&Qs[k0 + 8];
                qf[mt][s][3] = *(const uint32_t*)&Qs[k0 + 8 * AS_H + 8];
            }
        }
    }
    __syncthreads();

    float oacc[2][8][4];
#pragma unroll
    for (int mt = 0; mt < 2; mt++)
#pragma unroll
        for (int nt = 0; nt < 8; nt++)
#pragma unroll
            for (int i = 0; i < 4; i++) oacc[mt][nt][i] = 0.0f;
    float m[2][2] = { {-CUDART_INF_F, -CUDART_INF_F}, {-CUDART_INF_F, -CUDART_INF_F} };
    float l[2][2] = { {0.0f, 0.0f}, {0.0f, 0.0f} };

    auto load_kv = [&](int kt2, int p) {
        const __half* kb = qkv + rowbase + (size_t)(kt2 * KTL) * QKV_N + EMB + h * HDIM;
        const __half* vb = vtbase + kt2 * KTL;   // V^T rows = dims, keys contiguous
        uint32_t kdst = sb + (p ? SM_K1 : SM_K0) * 2;
        uint32_t vdst = sb + (p ? SM_V1 : SM_V0) * 2;
#pragma unroll
        for (int i = 0; i < 4; i++) {
            int c = tid + 128 * i;            // 512 chunks each (64 rows x 8)
            int row = c >> 3, c8 = c & 7;
            cp16(kdst + row * (AS_H * 2) + c8 * 16, kb + (size_t)row * QKV_N + c8 * 8);
            cp16(vdst + row * (AS_H * 2) + c8 * 16, vb + (size_t)row * SEQ + c8 * 8);
        }
        asm volatile("cp.async.commit_group;");
    };

    load_kv(0, 0);
    load_kv(1, 1);

    for (int kt = 0; kt < SEQ / KTL; kt++) {
        const int p = kt & 1;
        asm volatile("cp.async.wait_group 1;");
        __syncthreads();
        const __half* Ks = shh + (p ? SM_K1 : SM_K0);
        const __half* Vs = shh + (p ? SM_V1 : SM_V0);

        // S = Q @ K^T (raw, unscaled). B-frag: b0=K[key nt*8+g][d 16s+2t..],
        // b1 = +8 dims. Each B fragment feeds both m-tiles.
        float sacc[2][8][4];
#pragma unroll
        for (int mt = 0; mt < 2; mt++)
#pragma unroll
            for (int nt = 0; nt < 8; nt++)
#pragma unroll
                for (int i = 0; i < 4; i++) sacc[mt][nt][i] = 0.0f;
#pragma unroll
        for (int s = 0; s < 4; s++) {
            const int kc = 16 * s + 2 * t;
#pragma unroll
            for (int nt = 0; nt < 8; nt++) {
                int r0 = (nt * 8 + g) * AS_H + kc;
                uint32_t bb[2];
                bb[0] = *(const uint32_t*)&Ks[r0];
                bb[1] = *(const uint32_t*)&Ks[r0 + 8];
                mma_f16(sacc[0][nt], qf[0][s], bb);
                mma_f16(sacc[1][nt], qf[1][s], bb);
            }
        }

        // running max in scaled domain (scale 1/8 exact)
        float mn[2][2], al[2][2];
#pragma unroll
        for (int mt = 0; mt < 2; mt++) {
            float mt0 = -CUDART_INF_F, mt1 = -CUDART_INF_F;
#pragma unroll
            for (int nt = 0; nt < 8; nt++) {
                mt0 = fmaxf(mt0, fmaxf(sacc[mt][nt][0], sacc[mt][nt][1]));
                mt1 = fmaxf(mt1, fmaxf(sacc[mt][nt][2], sacc[mt][nt][3]));
            }
            mt0 = fmaxf(mt0, __shfl_xor_sync(0xffffffffu, mt0, 1));
            mt0 = fmaxf(mt0, __shfl_xor_sync(0xffffffffu, mt0, 2));
            mt1 = fmaxf(mt1, __shfl_xor_sync(0xffffffffu, mt1, 1));
            mt1 = fmaxf(mt1, __shfl_xor_sync(0xffffffffu, mt1, 2));
            mn[mt][0] = fmaxf(m[mt][0], 0.125f * mt0);
            mn[mt][1] = fmaxf(m[mt][1], 0.125f * mt1);
            al[mt][0] = __expf(m[mt][0] - mn[mt][0]);
            al[mt][1] = __expf(m[mt][1] - mn[mt][1]);
            m[mt][0] = mn[mt][0];
            m[mt][1] = mn[mt][1];
#pragma unroll
            for (int nt = 0; nt < 8; nt++) {
                oacc[mt][nt][0] *= al[mt][0]; oacc[mt][nt][1] *= al[mt][0];
                oacc[mt][nt][2] *= al[mt][1]; oacc[mt][nt][3] *= al[mt][1];
            }
        }

        // FUSED softmax + PV. PV k16 step s covers keys [16s,16s+16):
        // A-frag = exps of sacc[.][2s] (k 0..7) and sacc[.][2s+1] (k 8..15),
        // packed half2. B-frag: b0 = V^T[dim ot*8+g][key 16s+2t..+1], b1=+8.
        float sum[2][2] = { {0.0f, 0.0f}, {0.0f, 0.0f} };
#pragma unroll
        for (int s = 0; s < 4; s++) {
            uint32_t a0[4], a1[4];
#pragma unroll
            for (int mt = 0; mt < 2; mt++) {
                uint32_t* aa = mt ? a1 : a0;
                float e00 = __expf(fmaf(0.125f, sacc[mt][2 * s][0], -mn[mt][0]));
                float e01 = __expf(fmaf(0.125f, sacc[mt][2 * s][1], -mn[mt][0]));
                float e10 = __expf(fmaf(0.125f, sacc[mt][2 * s][2], -mn[mt][1]));
                float e11 = __expf(fmaf(0.125f, sacc[mt][2 * s][3], -mn[mt][1]));
                float f00 = __expf(fmaf(0.125f, sacc[mt][2 * s + 1][0], -mn[mt][0]));
                float f01 = __expf(fmaf(0.125f, sacc[mt][2 * s + 1][1], -mn[mt][0]));
                float f10 = __expf(fmaf(0.125f, sacc[mt][2 * s + 1][2], -mn[mt][1]));
                float f11 = __expf(fmaf(0.125f, sacc[mt][2 * s + 1][3], -mn[mt][1]));
                sum[mt][0] += (e00 + e01) + (f00 + f01);
                sum[mt][1] += (e10 + e11) + (f10 + f11);
                aa[0] = pack_h2(e00, e01);
                aa[1] = pack_h2(e10, e11);
                aa[2] = pack_h2(f00, f01);
                aa[3] = pack_h2(f10, f11);
            }
            const int kc = 16 * s + 2 * t;
#pragma unroll
            for (int ot = 0; ot < 8; ot++) {
                int r0 = (ot * 8 + g) * AS_H + kc;
                uint32_t bb[2];
                bb[0] = *(const uint32_t*)&Vs[r0];
                bb[1] = *(const uint32_t*)&Vs[r0 + 8];
                mma_f16(oacc[0][ot], a0, bb);
                mma_f16(oacc[1][ot], a1, bb);
            }
        }
#pragma unroll
        for (int mt = 0; mt < 2; mt++) {
            float s0 = sum[mt][0], s1 = sum[mt][1];
            s0 += __shfl_xor_sync(0xffffffffu, s0, 1);
            s0 += __shfl_xor_sync(0xffffffffu, s0, 2);
            s1 += __shfl_xor_sync(0xffffffffu, s1, 1);
            s1 += __shfl_xor_sync(0xffffffffu, s1, 2);
            l[mt][0] = l[mt][0] * al[mt][0] + s0;
            l[mt][1] = l[mt][1] * al[mt][1] + s1;
        }

        __syncthreads();   // everyone done with buffer p
        if (kt + 2 < SEQ / KTL) load_kv(kt + 2, p);
        else asm volatile("cp.async.commit_group;");
    }

    // epilogue: normalize, write fp16 [B,S,E] (feeds fp16 out-projection)
#pragma unroll
    for (int mt = 0; mt < 2; mt++) {
        const float inv0 = 1.0f / l[mt][0], inv1 = 1.0f / l[mt][1];
        __half* orow0 = out + (size_t)(b * SEQ + q0 + wid * 32 + mt * 16 + g) * EMB + h * HDIM;
        __half* orow1 = orow0 + (size_t)8 * EMB;
#pragma unroll
        for (int nt = 0; nt < 8; nt++) {
            const int col = nt * 8 + 2 * t;
            *(__half2*)&orow0[col] =
                __floats2half2_rn(oacc[mt][nt][0] * inv0, oacc[mt][nt][1] * inv0);
            *(__half2*)&orow1[col] =
                __floats2half2_rn(oacc[mt][nt][2] * inv1, oacc[mt][nt][3] * inv1);
        }
    }
}

// ---------------------------------------------------------------------------
// launch
// ---------------------------------------------------------------------------
extern "C" void kernel_launch(void* const* d_in, const int* in_sizes, int n_in,
                              void* d_out, int out_size)
{
    const float* x     = (const float*)d_in[0];  // [2,2048,1024]
    const float* W_qkv = (const float*)d_in[1];  // [1024,3072]
    const float* b_qkv = (const float*)d_in[2];  // [3072]
    const float* W_out = (const float*)d_in[3];  // [1024,1024]
    const float* b_out = (const float*)d_in[4];  // [1024]
    float* out = (float*)d_out;                  // [2,2048,1024]

    __half *qkvh, *attnh, *xh, *wqth, *woth, *vth;
    cudaGetSymbolAddress((void**)&qkvh,  g_qkvh);
    cudaGetSymbolAddress((void**)&attnh, g_attnh);
    cudaGetSymbolAddress((void**)&xh,    g_xh);
    cudaGetSymbolAddress((void**)&wqth,  g_wqth);
    cudaGetSymbolAddress((void**)&woth,  g_woth);
    cudaGetSymbolAddress((void**)&vth,   g_vth);

    // 0) prep: fp16 conversion of x, transposed+converted weights
    f2h_kernel<<<(ROWS * EMB / 4 + 255) / 256, 256>>>(
        (const float4*)x, (__half2*)xh, ROWS * EMB / 4);
    transpose_h_kernel<<<dim3(QKV_N / 32, EMB / 32), dim3(32, 8)>>>(W_qkv, wqth, EMB, QKV_N);
    transpose_h_kernel<<<dim3(EMB / 32, EMB / 32), dim3(32, 8)>>>(W_out, woth, EMB, EMB);

    cudaFuncSetAttribute(gemm_h_kernel<true>,
                         cudaFuncAttributeMaxDynamicSharedMemorySize, GK_DSMEM);
    cudaFuncSetAttribute(gemm_h_kernel<false>,
                         cudaFuncAttributeMaxDynamicSharedMemorySize, GK_DSMEM);
    cudaFuncSetAttribute(attn_tc_kernel,
                         cudaFuncAttributeMaxDynamicSharedMemorySize, ATTN_SMEM_BYTES);

    // 1) QKV projection (fp16 in/out, fp32 accumulate)
    gemm_h_kernel<true><<<dim3(QKV_N / 128, ROWS / 128), 128, GK_DSMEM>>>(
        xh, wqth, b_qkv, qkvh, EMB, QKV_N);

    // 1b) per-head V transpose (PV B-fragment needs keys contiguous)
    vth_transpose_kernel<<<dim3(SEQ / 32, HDIM / 32, BSZ * NHEAD), dim3(32, 8)>>>(qkvh, vth);

    // 2) fp16 tensor-core flash attention
    attn_tc_kernel<<<dim3(SEQ / 128, NHEAD, BSZ), 128, ATTN_SMEM_BYTES>>>(qkvh, vth, attnh);

    // 3) output projection (fp16 in, fp32 out)
    gemm_h_kernel<false><<<dim3(EMB / 128, ROWS / 128), 128, GK_DSMEM>>>(
        attnh, woth, b_out, out, EMB, EMB);
}